// round 1
// baseline (speedup 1.0000x reference)
#include <cuda_runtime.h>
#include <math.h>
#include <float.h>

#define N_ROWS 100000
#define DDIM 1024
#define ADIM 128
#define HDIM 256
#define KSEL 16

// ---- scratch (static device globals; no allocation) ----
__device__ float g_scores[N_ROWS];
__device__ float g_cand_v[1600];
__device__ int   g_cand_i[1600];
__device__ int   g_topidx[KSEL];
__device__ float g_attnw[KSEL];
__device__ float g_emb[DDIM];

// ============================================================
// Kernel A: fused scores = tanh(x@Wa1 + ba1) @ Wa2 + ba2
// Register-tiled SGEMM: BM=64 rows, BN=128 (=A, full), BK=16.
// 256 threads, each owns a 4x8 accumulator tile.
// ============================================================
__global__ void __launch_bounds__(256) scores_kernel(
    const float* __restrict__ x, const float* __restrict__ Wa1,
    const float* __restrict__ ba1, const float* __restrict__ Wa2,
    const float* __restrict__ ba2)
{
    __shared__ float As[16][64];    // k-major so compute loads 4 consecutive m
    __shared__ float Bs[16][128];

    const int t = threadIdx.x;
    const int block_m = blockIdx.x * 64;

    const int r = t >> 4;           // 0..15  -> rows r*4..r*4+3
    const int c = t & 15;           // 0..15  -> cols c*8..c*8+7

    float acc[4][8];
#pragma unroll
    for (int i = 0; i < 4; i++)
#pragma unroll
        for (int j = 0; j < 8; j++) acc[i][j] = 0.f;

    // load mapping for the x tile
    const int lm = t >> 2;          // 0..63 (row in tile)
    const int lk = (t & 3) * 4;     // 0,4,8,12 (k offset)
    const int row = block_m + lm;
    const bool rowok = (row < N_ROWS);

    const int kt0 = t >> 5;         // 0..7 for Wa1 tile load
    const int nb  = (t & 31) * 4;   // 0..124

    for (int k0 = 0; k0 < DDIM; k0 += 16) {
        float4 av = rowok ? *(const float4*)&x[(size_t)row * DDIM + k0 + lk]
                          : make_float4(0.f, 0.f, 0.f, 0.f);
        As[lk + 0][lm] = av.x;
        As[lk + 1][lm] = av.y;
        As[lk + 2][lm] = av.z;
        As[lk + 3][lm] = av.w;

        *(float4*)&Bs[kt0    ][nb] = *(const float4*)&Wa1[(size_t)(k0 + kt0    ) * ADIM + nb];
        *(float4*)&Bs[kt0 + 8][nb] = *(const float4*)&Wa1[(size_t)(k0 + kt0 + 8) * ADIM + nb];

        __syncthreads();

#pragma unroll
        for (int k = 0; k < 16; k++) {
            float4 a  = *(const float4*)&As[k][r * 4];
            float4 b0 = *(const float4*)&Bs[k][c * 8];
            float4 b1 = *(const float4*)&Bs[k][c * 8 + 4];
            float av_[4] = {a.x, a.y, a.z, a.w};
            float bv_[8] = {b0.x, b0.y, b0.z, b0.w, b1.x, b1.y, b1.z, b1.w};
#pragma unroll
            for (int i = 0; i < 4; i++)
#pragma unroll
                for (int j = 0; j < 8; j++)
                    acc[i][j] = fmaf(av_[i], bv_[j], acc[i][j]);
        }
        __syncthreads();
    }

    // epilogue: tanh, contract with Wa2, reduce over the 16 col-threads
    float w2[8], b1v[8];
#pragma unroll
    for (int j = 0; j < 8; j++) {
        w2[j]  = Wa2[c * 8 + j];
        b1v[j] = ba1[c * 8 + j];
    }
    const float bias2 = ba2[0];

#pragma unroll
    for (int i = 0; i < 4; i++) {
        float p = 0.f;
#pragma unroll
        for (int j = 0; j < 8; j++)
            p += tanhf(acc[i][j] + b1v[j]) * w2[j];
        // reduce across the 16 threads sharing this row (contiguous lanes)
#pragma unroll
        for (int off = 8; off >= 1; off >>= 1)
            p += __shfl_down_sync(0xffffffffu, p, off, 16);
        if (c == 0) {
            int rr = block_m + r * 4 + i;
            if (rr < N_ROWS) g_scores[rr] = p + bias2;
        }
    }
}

// ============================================================
// zero the full_weights region of the output
// ============================================================
__global__ void zero_fw(float* __restrict__ out)
{
    int i = blockIdx.x * blockDim.x + threadIdx.x;
    if (i < N_ROWS) out[1 + DDIM + i] = 0.f;
}

// ============================================================
// Top-K stage 1: 100 blocks x 1000 elems -> block-local top-16
// exact iterative argmax with lowest-index tie-break (jax semantics)
// ============================================================
__global__ void __launch_bounds__(256) topk_stage1()
{
    __shared__ float sv[1000];
    __shared__ float rv[256];
    __shared__ int   ri[256];

    const int t = threadIdx.x;
    const int base = blockIdx.x * 1000;

    for (int i = t; i < 1000; i += 256) sv[i] = g_scores[base + i];
    __syncthreads();

    for (int it = 0; it < KSEL; it++) {
        float bv = -FLT_MAX;
        int   bi = 0x7fffffff;
        for (int i = t; i < 1000; i += 256) {
            float v = sv[i];
            if (v > bv) { bv = v; bi = i; }   // ascending i keeps lowest idx on tie
        }
        rv[t] = bv; ri[t] = bi;
        __syncthreads();
        for (int s = 128; s >= 1; s >>= 1) {
            if (t < s) {
                float ov = rv[t + s]; int oi = ri[t + s];
                if (ov > rv[t] || (ov == rv[t] && oi < ri[t])) { rv[t] = ov; ri[t] = oi; }
            }
            __syncthreads();
        }
        if (t == 0) {
            g_cand_v[blockIdx.x * KSEL + it] = rv[0];
            g_cand_i[blockIdx.x * KSEL + it] = base + ri[0];
            sv[ri[0]] = -FLT_MAX;
        }
        __syncthreads();
    }
}

// ============================================================
// Top-K stage 2: 1600 candidates -> final top-16, softmax,
// scatter full_weights, write top_idx
// ============================================================
__global__ void __launch_bounds__(256) topk_stage2(float* __restrict__ out)
{
    __shared__ float sv[1600];
    __shared__ int   si[1600];
    __shared__ float rv[256];
    __shared__ int   ri[256];
    __shared__ float topv[KSEL];
    __shared__ int   topi[KSEL];

    const int t = threadIdx.x;
    for (int i = t; i < 1600; i += 256) { sv[i] = g_cand_v[i]; si[i] = g_cand_i[i]; }
    __syncthreads();

    for (int it = 0; it < KSEL; it++) {
        float bv = -FLT_MAX;
        int   bi = 0x7fffffff;
        for (int i = t; i < 1600; i += 256) {
            float v = sv[i]; int gi = si[i];
            if (v > bv || (v == bv && gi < bi)) { bv = v; bi = gi; }
        }
        rv[t] = bv; ri[t] = bi;
        __syncthreads();
        for (int s = 128; s >= 1; s >>= 1) {
            if (t < s) {
                float ov = rv[t + s]; int oi = ri[t + s];
                if (ov > rv[t] || (ov == rv[t] && oi < ri[t])) { rv[t] = ov; ri[t] = oi; }
            }
            __syncthreads();
        }
        const float winv = rv[0];
        const int   wini = ri[0];
        if (t == 0) { topv[it] = winv; topi[it] = wini; }
        // mask the winner (candidate indices are unique)
        for (int i = t; i < 1600; i += 256)
            if (si[i] == wini) sv[i] = -FLT_MAX;
        __syncthreads();
    }

    if (t == 0) {
        float m = topv[0];             // descending -> [0] is max
        float e[KSEL];
        float s = 0.f;
        for (int j = 0; j < KSEL; j++) { e[j] = expf(topv[j] - m); s += e[j]; }
        float inv = 1.f / s;
        for (int j = 0; j < KSEL; j++) {
            float w = e[j] * inv;
            g_attnw[j]  = w;
            g_topidx[j] = topi[j];
            out[1 + DDIM + N_ROWS + j] = (float)topi[j];  // top_idx as output dtype
            out[1 + DDIM + topi[j]]    = w;               // scatter attn weights
        }
    }
}

// ============================================================
// slide_embedding = attn_w @ x[top_idx]   ([16] x [16,1024] -> [1024])
// ============================================================
__global__ void __launch_bounds__(256) emb_kernel(const float* __restrict__ x,
                                                  float* __restrict__ out)
{
    __shared__ float w[KSEL];
    __shared__ int   id[KSEL];
    const int t = threadIdx.x;
    if (t < KSEL) { w[t] = g_attnw[t]; id[t] = g_topidx[t]; }
    __syncthreads();

    for (int d = t; d < DDIM; d += 256) {
        float s = 0.f;
#pragma unroll
        for (int j = 0; j < KSEL; j++)
            s += w[j] * x[(size_t)id[j] * DDIM + d];
        g_emb[d]   = s;
        out[1 + d] = s;
    }
}

// ============================================================
// classifier: h = relu(emb @ Wc1 + bc1); logit = h @ Wc2 + bc2
// ============================================================
__global__ void __launch_bounds__(256) cls_kernel(
    const float* __restrict__ Wc1, const float* __restrict__ bc1,
    const float* __restrict__ Wc2, const float* __restrict__ bc2,
    float* __restrict__ out)
{
    __shared__ float e[DDIM];
    __shared__ float red[256];
    const int t = threadIdx.x;

    for (int d = t; d < DDIM; d += 256) e[d] = g_emb[d];
    __syncthreads();

    float acc = 0.f;
#pragma unroll 8
    for (int d = 0; d < DDIM; d++)
        acc = fmaf(e[d], Wc1[(size_t)d * HDIM + t], acc);
    float h = fmaxf(acc + bc1[t], 0.f);
    red[t] = h * Wc2[t];
    __syncthreads();
    for (int s = 128; s >= 1; s >>= 1) {
        if (t < s) red[t] += red[t + s];
        __syncthreads();
    }
    if (t == 0) out[0] = red[0] + bc2[0];
}

// ============================================================
extern "C" void kernel_launch(void* const* d_in, const int* in_sizes, int n_in,
                              void* d_out, int out_size)
{
    const float* x   = (const float*)d_in[0];
    const float* Wa1 = (const float*)d_in[1];
    const float* ba1 = (const float*)d_in[2];
    const float* Wa2 = (const float*)d_in[3];
    const float* ba2 = (const float*)d_in[4];
    const float* Wc1 = (const float*)d_in[5];
    const float* bc1 = (const float*)d_in[6];
    const float* Wc2 = (const float*)d_in[7];
    const float* bc2 = (const float*)d_in[8];
    float* out = (float*)d_out;

    scores_kernel<<<(N_ROWS + 63) / 64, 256>>>(x, Wa1, ba1, Wa2, ba2);
    zero_fw<<<(N_ROWS + 255) / 256, 256>>>(out);
    topk_stage1<<<100, 256>>>();
    topk_stage2<<<1, 256>>>(out);
    emb_kernel<<<1, 256>>>(x, out);
    cls_kernel<<<1, 256>>>(Wc1, bc1, Wc2, bc2, out);
}

// round 4
// speedup vs baseline: 2.4470x; 2.4470x over previous
#include <cuda_runtime.h>
#include <cuda_bf16.h>
#include <math.h>
#include <float.h>
#include <stdint.h>

#define N_ROWS 100000
#define DDIM 1024
#define ADIM 128
#define HDIM 256
#define KSEL 16
#define MAXC 4096
#define GEMM_BLKS 782       // ceil(100000/128)

// ================= scratch (device globals; no allocation) =================
__device__ float g_scores[N_ROWS];
__device__ __align__(16) __nv_bfloat16 g_Bbf[ADIM * DDIM];   // Wa1^T, bf16, [n][k]
__device__ unsigned g_hist[65536];
__device__ int      g_ncand;
__device__ unsigned g_thresh;
__device__ int      g_cand_i[MAXC];
__device__ float    g_cand_v[MAXC];
__device__ int      g_topidx[KSEL];
__device__ float    g_attnw[KSEL];
__device__ float    g_emb[DDIM];

__device__ __forceinline__ uint32_t smem_u32(const void* p) {
    uint32_t a;
    asm("{ .reg .u64 tmp; cvta.to.shared.u64 tmp, %1; cvt.u32.u64 %0, tmp; }"
        : "=r"(a) : "l"(p));
    return a;
}

__device__ __forceinline__ unsigned fliporder(float f) {
    unsigned u = __float_as_uint(f);
    return (u & 0x80000000u) ? ~u : (u | 0x80000000u);
}

// ================= pre-pass: Wa1 [k][n] fp32 -> g_Bbf [n][k] bf16 =================
__global__ void __launch_bounds__(256) conv_B(const float* __restrict__ Wa1) {
    int idx = blockIdx.x * 256 + threadIdx.x;   // 0..131071
    int n = idx & 127;
    int k = idx >> 7;
    g_Bbf[(size_t)n * DDIM + k] = __float2bfloat16(Wa1[(size_t)k * ADIM + n]);
}

// ================= zero: full_weights + histogram + counter =================
__global__ void __launch_bounds__(256) zero_misc(float* __restrict__ out) {
    int i = blockIdx.x * 256 + threadIdx.x;
    if (i < N_ROWS) out[1 + DDIM + i] = 0.f;
    if (i < 65536)  g_hist[i] = 0u;
    if (i == 0)     g_ncand = 0;
}

// ================= main GEMM: approx scores via mma.sync bf16 =================
// BM=128, BN=128(=ADIM), BK=32, 512 threads = 16 warps in 4x4 grid,
// warp tile 32x32, double-buffered smem + register prefetch.
#define SROW 40   // padded row stride (bf16 elems); row stride 80B -> 16B-aligned rows

__global__ void __launch_bounds__(512, 1) gemm_scores(
    const float* __restrict__ x, const float* __restrict__ ba1,
    const float* __restrict__ Wa2, const float* __restrict__ ba2)
{
    __shared__ __align__(16) __nv_bfloat16 sA[2][128][SROW];
    __shared__ __align__(16) __nv_bfloat16 sB[2][128][SROW];
    __shared__ float s_part[4][128];
    __shared__ float s_b1[ADIM], s_w2[ADIM];

    const int t = threadIdx.x;
    const int w = t >> 5, lane = t & 31;
    const int wm = w & 3, wn = w >> 2;
    const size_t block_m = (size_t)blockIdx.x * 128;

    if (t < ADIM) { s_b1[t] = ba1[t]; s_w2[t] = Wa2[t]; }

    // global load mapping: thread -> (row, 8-col group)
    const int lrow = t >> 2;                 // 0..127
    const int lcg  = (t & 3) * 8;            // 0,8,16,24
    const size_t grow = block_m + (size_t)lrow;
    const bool rowok = (grow < N_ROWS);
    const float* xA = x + (rowok ? grow : 0) * DDIM + lcg;
    const __nv_bfloat16* gB = g_Bbf + (size_t)lrow * DDIM + lcg;

    // ldmatrix lane address components
    // A (x4, no trans): m0=rows0-7/k0-7, m1=rows8-15/k0-7, m2=rows0-7/k8-15, m3=rows8-15/k8-15
    const int arow_l = ((lane >> 3) & 1) * 8 + (lane & 7);
    const int acol_l = (lane >> 4) * 8;
    // B (x4, NO trans; smem is [n][k] k-contiguous = col-major KxN):
    // m0=n0-7/k0-7 (b0 of nj0), m1=n0-7/k8-15 (b1 of nj0), m2=n8-15/k0-7, m3=n8-15/k8-15
    const int brow_l = ((lane >> 4) & 1) * 8 + (lane & 7);
    const int bcol_l = ((lane >> 3) & 1) * 8;

    const uint32_t sa_base = smem_u32(&sA[0][0][0]);
    const uint32_t sb_base = smem_u32(&sB[0][0][0]);
    const uint32_t bufstride = 128 * SROW * 2;

    float acc[2][4][4];
#pragma unroll
    for (int i = 0; i < 2; i++)
#pragma unroll
        for (int j = 0; j < 4; j++)
#pragma unroll
            for (int q = 0; q < 4; q++) acc[i][j][q] = 0.f;

    float4 pa0, pa1; uint4 pb;
    // prefetch chunk 0
    if (rowok) { pa0 = *(const float4*)(xA); pa1 = *(const float4*)(xA + 4); }
    else       { pa0 = make_float4(0,0,0,0); pa1 = pa0; }
    pb = *(const uint4*)(gB);

#pragma unroll 1
    for (int c = 0; c < 32; c++) {
        const int buf = c & 1;
        // store prefetched chunk to smem (convert A to bf16)
        {
            __nv_bfloat162 q0 = __floats2bfloat162_rn(pa0.x, pa0.y);
            __nv_bfloat162 q1 = __floats2bfloat162_rn(pa0.z, pa0.w);
            __nv_bfloat162 q2 = __floats2bfloat162_rn(pa1.x, pa1.y);
            __nv_bfloat162 q3 = __floats2bfloat162_rn(pa1.z, pa1.w);
            uint4 u;
            u.x = *(uint32_t*)&q0; u.y = *(uint32_t*)&q1;
            u.z = *(uint32_t*)&q2; u.w = *(uint32_t*)&q3;
            *(uint4*)&sA[buf][lrow][lcg] = u;
            *(uint4*)&sB[buf][lrow][lcg] = pb;
        }
        __syncthreads();

        // prefetch next chunk
        if (c < 31) {
            const int k0 = (c + 1) * 32;
            if (rowok) { pa0 = *(const float4*)(xA + k0); pa1 = *(const float4*)(xA + k0 + 4); }
            pb = *(const uint4*)(gB + k0);
        }

        // compute chunk c
        const uint32_t sa = sa_base + buf * bufstride;
        const uint32_t sb = sb_base + buf * bufstride;
#pragma unroll
        for (int ks = 0; ks < 2; ks++) {
            uint32_t a[2][4];
#pragma unroll
            for (int mi = 0; mi < 2; mi++) {
                uint32_t addr = sa + (((wm * 32 + mi * 16 + arow_l) * SROW) + ks * 16 + acol_l) * 2;
                asm volatile("ldmatrix.sync.aligned.m8n8.x4.shared.b16 {%0,%1,%2,%3}, [%4];"
                    : "=r"(a[mi][0]), "=r"(a[mi][1]), "=r"(a[mi][2]), "=r"(a[mi][3]) : "r"(addr));
            }
            uint32_t b[4][2];
#pragma unroll
            for (int njp = 0; njp < 2; njp++) {
                uint32_t addr = sb + (((wn * 32 + njp * 16 + brow_l) * SROW) + ks * 16 + bcol_l) * 2;
                uint32_t r0, r1, r2, r3;
                asm volatile("ldmatrix.sync.aligned.m8n8.x4.shared.b16 {%0,%1,%2,%3}, [%4];"
                    : "=r"(r0), "=r"(r1), "=r"(r2), "=r"(r3) : "r"(addr));
                b[njp * 2 + 0][0] = r0; b[njp * 2 + 0][1] = r1;
                b[njp * 2 + 1][0] = r2; b[njp * 2 + 1][1] = r3;
            }
#pragma unroll
            for (int mi = 0; mi < 2; mi++)
#pragma unroll
                for (int nj = 0; nj < 4; nj++) {
                    asm volatile(
                        "mma.sync.aligned.m16n8k16.row.col.f32.bf16.bf16.f32 "
                        "{%0,%1,%2,%3}, {%4,%5,%6,%7}, {%8,%9}, {%0,%1,%2,%3};"
                        : "+f"(acc[mi][nj][0]), "+f"(acc[mi][nj][1]),
                          "+f"(acc[mi][nj][2]), "+f"(acc[mi][nj][3])
                        : "r"(a[mi][0]), "r"(a[mi][1]), "r"(a[mi][2]), "r"(a[mi][3]),
                          "r"(b[nj][0]), "r"(b[nj][1]));
                }
        }
        __syncthreads();
    }

    // ---- epilogue: score = sum_n tanh(D + b1[n]) * w2[n] ----
#pragma unroll
    for (int mi = 0; mi < 2; mi++) {
        float p0 = 0.f, p1 = 0.f;
#pragma unroll
        for (int nj = 0; nj < 4; nj++) {
            int col = wn * 32 + nj * 8 + (lane & 3) * 2;
            float th;
            float v0 = acc[mi][nj][0] + s_b1[col];
            asm("tanh.approx.f32 %0, %1;" : "=f"(th) : "f"(v0));
            p0 = fmaf(th, s_w2[col], p0);
            float v1 = acc[mi][nj][1] + s_b1[col + 1];
            asm("tanh.approx.f32 %0, %1;" : "=f"(th) : "f"(v1));
            p0 = fmaf(th, s_w2[col + 1], p0);
            float v2 = acc[mi][nj][2] + s_b1[col];
            asm("tanh.approx.f32 %0, %1;" : "=f"(th) : "f"(v2));
            p1 = fmaf(th, s_w2[col], p1);
            float v3 = acc[mi][nj][3] + s_b1[col + 1];
            asm("tanh.approx.f32 %0, %1;" : "=f"(th) : "f"(v3));
            p1 = fmaf(th, s_w2[col + 1], p1);
        }
        p0 += __shfl_xor_sync(0xffffffffu, p0, 1);
        p0 += __shfl_xor_sync(0xffffffffu, p0, 2);
        p1 += __shfl_xor_sync(0xffffffffu, p1, 1);
        p1 += __shfl_xor_sync(0xffffffffu, p1, 2);
        if ((lane & 3) == 0) {
            int r = wm * 32 + mi * 16 + (lane >> 2);
            s_part[wn][r]     = p0;
            s_part[wn][r + 8] = p1;
        }
    }
    __syncthreads();
    if (t < 128) {
        size_t m = block_m + (size_t)t;
        if (m < N_ROWS)
            g_scores[m] = s_part[0][t] + s_part[1][t] + s_part[2][t] + s_part[3][t] + ba2[0];
    }
}

// ================= histogram / threshold / collect =================
__global__ void __launch_bounds__(512) hist_k() {
    int i = blockIdx.x * 512 + threadIdx.x;
    if (i < N_ROWS) atomicAdd(&g_hist[fliporder(g_scores[i]) >> 16], 1u);
}

__global__ void __launch_bounds__(256) scan_k() {
    __shared__ unsigned part[256];
    __shared__ unsigned segbins[256];
    __shared__ int s_seg;
    __shared__ unsigned s_cum;
    int t = threadIdx.x;
    unsigned sum = 0;
#pragma unroll 8
    for (int j = 0; j < 256; j++) sum += g_hist[t * 256 + j];
    part[t] = sum;
    __syncthreads();
    if (t == 0) {
        unsigned cum = 0; int seg = 255;
        for (; seg > 0; seg--) { if (cum + part[seg] >= 64u) break; cum += part[seg]; }
        s_seg = seg; s_cum = cum;
    }
    __syncthreads();
    segbins[t] = g_hist[s_seg * 256 + t];
    __syncthreads();
    if (t == 0) {
        unsigned cum = s_cum; int b = 255;
        for (; b > 0; b--) { cum += segbins[b]; if (cum >= 64u) break; }
        g_thresh = ((unsigned)(s_seg * 256 + b)) << 16;
    }
}

__global__ void __launch_bounds__(512) collect_k() {
    int i = blockIdx.x * 512 + threadIdx.x;
    if (i < N_ROWS && fliporder(g_scores[i]) >= g_thresh) {
        int p = atomicAdd(&g_ncand, 1);
        if (p < MAXC) g_cand_i[p] = i;
    }
}

// ================= exact fp32 rescore of candidates =================
__global__ void __launch_bounds__(128) rescore_k(
    const float* __restrict__ x, const float* __restrict__ Wa1,
    const float* __restrict__ ba1, const float* __restrict__ Wa2,
    const float* __restrict__ ba2)
{
    __shared__ float sx[DDIM];
    __shared__ float sred[4];
    int nc = g_ncand; if (nc > MAXC) nc = MAXC;
    const int t = threadIdx.x;
    for (int c = blockIdx.x; c < nc; c += gridDim.x) {
        int row = g_cand_i[c];
        for (int j = t; j < DDIM; j += 128) sx[j] = x[(size_t)row * DDIM + j];
        __syncthreads();
        float a = 0.f;
#pragma unroll 8
        for (int k = 0; k < DDIM; k++)
            a = fmaf(sx[k], Wa1[(size_t)k * ADIM + t], a);
        float v = tanhf(a + ba1[t]) * Wa2[t];
#pragma unroll
        for (int off = 16; off >= 1; off >>= 1) v += __shfl_down_sync(0xffffffffu, v, off);
        if ((t & 31) == 0) sred[t >> 5] = v;
        __syncthreads();
        if (t == 0) g_cand_v[c] = sred[0] + sred[1] + sred[2] + sred[3] + ba2[0];
        __syncthreads();
    }
}

// ================= exact final top-16 + softmax + scatter =================
__global__ void __launch_bounds__(256) final_k(float* __restrict__ out) {
    __shared__ float sv[MAXC];
    __shared__ int   si[MAXC];
    __shared__ float wv[8];
    __shared__ int   wi[8];
    __shared__ float topv[KSEL];
    __shared__ int   topi[KSEL];
    const int t = threadIdx.x;
    int nc = g_ncand; if (nc > MAXC) nc = MAXC;
    for (int i = t; i < MAXC; i += 256) {
        sv[i] = (i < nc) ? g_cand_v[i] : -FLT_MAX;
        si[i] = (i < nc) ? g_cand_i[i] : 0x7fffffff;
    }
    __syncthreads();
    for (int it = 0; it < KSEL; it++) {
        float bv = -FLT_MAX; int bi = 0x7fffffff;
        for (int i = t; i < MAXC; i += 256) {
            float v = sv[i]; int gi = si[i];
            if (v > bv || (v == bv && gi < bi)) { bv = v; bi = gi; }
        }
#pragma unroll
        for (int off = 16; off >= 1; off >>= 1) {
            float ov = __shfl_down_sync(0xffffffffu, bv, off);
            int   oi = __shfl_down_sync(0xffffffffu, bi, off);
            if (ov > bv || (ov == bv && oi < bi)) { bv = ov; bi = oi; }
        }
        if ((t & 31) == 0) { wv[t >> 5] = bv; wi[t >> 5] = bi; }
        __syncthreads();
        if (t == 0) {
            for (int w = 1; w < 8; w++)
                if (wv[w] > wv[0] || (wv[w] == wv[0] && wi[w] < wi[0])) { wv[0] = wv[w]; wi[0] = wi[w]; }
            topv[it] = wv[0]; topi[it] = wi[0];
        }
        __syncthreads();
        int wini = topi[it];
        for (int i = t; i < MAXC; i += 256)
            if (si[i] == wini) sv[i] = -FLT_MAX;
        __syncthreads();
    }
    if (t == 0) {
        float m = topv[0];
        float e[KSEL];
        float ssum = 0.f;
        for (int j = 0; j < KSEL; j++) { e[j] = expf(topv[j] - m); ssum += e[j]; }
        float inv = 1.f / ssum;
        for (int j = 0; j < KSEL; j++) {
            float w = e[j] * inv;
            g_attnw[j]  = w;
            g_topidx[j] = topi[j];
            out[1 + DDIM + N_ROWS + j] = (float)topi[j];
            out[1 + DDIM + topi[j]]    = w;
        }
    }
}

// ================= embedding + classifier =================
__global__ void __launch_bounds__(256) emb_kernel(const float* __restrict__ x,
                                                  float* __restrict__ out) {
    __shared__ float w[KSEL];
    __shared__ int   id[KSEL];
    const int t = threadIdx.x;
    if (t < KSEL) { w[t] = g_attnw[t]; id[t] = g_topidx[t]; }
    __syncthreads();
    for (int d = t; d < DDIM; d += 256) {
        float s = 0.f;
#pragma unroll
        for (int j = 0; j < KSEL; j++)
            s += w[j] * x[(size_t)id[j] * DDIM + d];
        g_emb[d]   = s;
        out[1 + d] = s;
    }
}

__global__ void __launch_bounds__(256) cls_kernel(
    const float* __restrict__ Wc1, const float* __restrict__ bc1,
    const float* __restrict__ Wc2, const float* __restrict__ bc2,
    float* __restrict__ out)
{
    __shared__ float e[DDIM];
    __shared__ float red[256];
    const int t = threadIdx.x;
    for (int d = t; d < DDIM; d += 256) e[d] = g_emb[d];
    __syncthreads();
    float acc = 0.f;
#pragma unroll 8
    for (int d = 0; d < DDIM; d++)
        acc = fmaf(e[d], Wc1[(size_t)d * HDIM + t], acc);
    float h = fmaxf(acc + bc1[t], 0.f);
    red[t] = h * Wc2[t];
    __syncthreads();
    for (int s = 128; s >= 1; s >>= 1) {
        if (t < s) red[t] += red[t + s];
        __syncthreads();
    }
    if (t == 0) out[0] = red[0] + bc2[0];
}

// ================= launch =================
extern "C" void kernel_launch(void* const* d_in, const int* in_sizes, int n_in,
                              void* d_out, int out_size)
{
    const float* x   = (const float*)d_in[0];
    const float* Wa1 = (const float*)d_in[1];
    const float* ba1 = (const float*)d_in[2];
    const float* Wa2 = (const float*)d_in[3];
    const float* ba2 = (const float*)d_in[4];
    const float* Wc1 = (const float*)d_in[5];
    const float* bc1 = (const float*)d_in[6];
    const float* Wc2 = (const float*)d_in[7];
    const float* bc2 = (const float*)d_in[8];
    float* out = (float*)d_out;

    conv_B<<<512, 256>>>(Wa1);
    zero_misc<<<391, 256>>>(out);
    gemm_scores<<<GEMM_BLKS, 512>>>(x, ba1, Wa2, ba2);
    hist_k<<<(N_ROWS + 511) / 512, 512>>>();
    scan_k<<<1, 256>>>();
    collect_k<<<(N_ROWS + 511) / 512, 512>>>();
    rescore_k<<<128, 128>>>(x, Wa1, ba1, Wa2, ba2);
    final_k<<<1, 256>>>(out);
    emb_kernel<<<1, 256>>>(x, out);
    cls_kernel<<<1, 256>>>(Wc1, bc1, Wc2, bc2, out);
}

// round 5
// speedup vs baseline: 3.0665x; 1.2532x over previous
#include <cuda_runtime.h>
#include <cuda_bf16.h>
#include <math.h>
#include <float.h>
#include <stdint.h>

#define N_ROWS 100000
#define DDIM 1024
#define ADIM 128
#define HDIM 256
#define KSEL 16
#define MAXC 4096
#define GEMM_BLKS 782       // ceil(100000/128)

// ================= scratch (device globals; no allocation) =================
__device__ float g_scores[N_ROWS];
__device__ __align__(16) __nv_bfloat16 g_Bbf[ADIM * DDIM];   // Wa1^T, bf16, [n][k]
__device__ unsigned g_hist[65536];
__device__ int      g_ncand;
__device__ unsigned g_thresh;
__device__ int      g_cand_i[MAXC];
__device__ float    g_cand_v[MAXC];
__device__ int      g_topidx[KSEL];
__device__ float    g_attnw[KSEL];
__device__ float    g_emb[DDIM];

__device__ __forceinline__ uint32_t smem_u32(const void* p) {
    uint32_t a;
    asm("{ .reg .u64 tmp; cvta.to.shared.u64 tmp, %1; cvt.u32.u64 %0, tmp; }"
        : "=r"(a) : "l"(p));
    return a;
}

__device__ __forceinline__ unsigned fliporder(float f) {
    unsigned u = __float_as_uint(f);
    return (u & 0x80000000u) ? ~u : (u | 0x80000000u);
}

// ================= pre-pass: Wa1 [k][n] fp32 -> g_Bbf [n][k] bf16 =================
__global__ void __launch_bounds__(256) conv_B(const float* __restrict__ Wa1) {
    int idx = blockIdx.x * 256 + threadIdx.x;   // 0..131071
    int n = idx & 127;
    int k = idx >> 7;
    g_Bbf[(size_t)n * DDIM + k] = __float2bfloat16(Wa1[(size_t)k * ADIM + n]);
}

// ================= zero: full_weights + histogram + counter =================
__global__ void __launch_bounds__(256) zero_misc(float* __restrict__ out) {
    int i = blockIdx.x * 256 + threadIdx.x;
    if (i < N_ROWS) out[1 + DDIM + i] = 0.f;
    if (i < 65536)  g_hist[i] = 0u;
    if (i == 0)     g_ncand = 0;
}

// ================= main GEMM: approx scores via mma.sync bf16 =================
// BM=128, BN=128(=ADIM), BK=32, 256 threads = 8 warps (2 M-halves x 4 N-slices),
// warp tile 64x32, double-buffered smem, cp.async for B, 2 CTAs/SM.
#define SROW 40   // padded row stride (bf16); 80B rows, 16B-aligned offsets

__global__ void __launch_bounds__(256, 2) gemm_scores(
    const float* __restrict__ x, const float* __restrict__ ba1,
    const float* __restrict__ Wa2, const float* __restrict__ ba2)
{
    __shared__ __align__(16) __nv_bfloat16 sA[2][128][SROW];
    __shared__ __align__(16) __nv_bfloat16 sB[2][128][SROW];
    __shared__ float s_part[4][128];
    __shared__ float s_b1[ADIM], s_w2[ADIM];

    const int t = threadIdx.x;
    const int w = t >> 5, lane = t & 31;
    const int wm = w & 1, wn = w >> 1;          // wm: M-half (64 rows), wn: N-slice (32 cols)
    const size_t block_m = (size_t)blockIdx.x * 128;

    if (t < ADIM) { s_b1[t] = ba1[t]; s_w2[t] = Wa2[t]; }

    // A global-load mapping: 4 slots/thread, slot i -> row arow+32*i, cols acol..acol+3
    const int arow = t >> 3;                    // 0..31
    const int acol = (t & 7) * 4;               // 0..28
    const float* xptr = x + (block_m + (size_t)arow) * DDIM + acol;
    bool aok[4];
#pragma unroll
    for (int i = 0; i < 4; i++) aok[i] = (block_m + arow + 32 * i) < N_ROWS;

    // B cp.async mapping: 2 slots/thread, slot j -> row brow+64*j, 16B at bcol8
    const int brow = t >> 2;                    // 0..63
    const int bcol8 = (t & 3) * 8;              // bf16 col offset 0,8,16,24
    const __nv_bfloat16* gB = g_Bbf + (size_t)brow * DDIM + bcol8;

    // ldmatrix lane address components (identical fragment logic to round 4)
    const int arow_l = ((lane >> 3) & 1) * 8 + (lane & 7);
    const int acol_l = (lane >> 4) * 8;
    const int brow_l = ((lane >> 4) & 1) * 8 + (lane & 7);
    const int bcol_l = ((lane >> 3) & 1) * 8;

    const uint32_t sa_base = smem_u32(&sA[0][0][0]);
    const uint32_t sb_base = smem_u32(&sB[0][0][0]);
    const uint32_t bufstride = 128 * SROW * 2;

    float acc[4][4][4];
#pragma unroll
    for (int i = 0; i < 4; i++)
#pragma unroll
        for (int j = 0; j < 4; j++)
#pragma unroll
            for (int q = 0; q < 4; q++) acc[i][j][q] = 0.f;

    // ---- prologue: prefetch chunk 0 ----
    float4 pa0, pa1, pa2, pa3;
    pa0 = aok[0] ? *(const float4*)(xptr)               : make_float4(0,0,0,0);
    pa1 = aok[1] ? *(const float4*)(xptr + 32 * DDIM)   : make_float4(0,0,0,0);
    pa2 = aok[2] ? *(const float4*)(xptr + 64 * DDIM)   : make_float4(0,0,0,0);
    pa3 = aok[3] ? *(const float4*)(xptr + 96 * DDIM)   : make_float4(0,0,0,0);
    {
        uint32_t d0 = sb_base + (uint32_t)((brow * SROW + bcol8) * 2);
        uint32_t d1 = sb_base + (uint32_t)(((brow + 64) * SROW + bcol8) * 2);
        asm volatile("cp.async.cg.shared.global [%0], [%1], 16;" :: "r"(d0), "l"(gB) : "memory");
        asm volatile("cp.async.cg.shared.global [%0], [%1], 16;" :: "r"(d1), "l"(gB + 64 * DDIM) : "memory");
        asm volatile("cp.async.commit_group;" ::: "memory");
    }

#pragma unroll 1
    for (int c = 0; c < 32; c++) {
        const int buf = c & 1;
        // store prefetched A (convert to bf16)
        {
            __nv_bfloat16* base = &sA[buf][0][0];
            __nv_bfloat162 q0 = __floats2bfloat162_rn(pa0.x, pa0.y);
            __nv_bfloat162 q1 = __floats2bfloat162_rn(pa0.z, pa0.w);
            *(uint2*)(base + arow * SROW + acol) = make_uint2(*(uint32_t*)&q0, *(uint32_t*)&q1);
            q0 = __floats2bfloat162_rn(pa1.x, pa1.y); q1 = __floats2bfloat162_rn(pa1.z, pa1.w);
            *(uint2*)(base + (arow + 32) * SROW + acol) = make_uint2(*(uint32_t*)&q0, *(uint32_t*)&q1);
            q0 = __floats2bfloat162_rn(pa2.x, pa2.y); q1 = __floats2bfloat162_rn(pa2.z, pa2.w);
            *(uint2*)(base + (arow + 64) * SROW + acol) = make_uint2(*(uint32_t*)&q0, *(uint32_t*)&q1);
            q0 = __floats2bfloat162_rn(pa3.x, pa3.y); q1 = __floats2bfloat162_rn(pa3.z, pa3.w);
            *(uint2*)(base + (arow + 96) * SROW + acol) = make_uint2(*(uint32_t*)&q0, *(uint32_t*)&q1);
        }
        asm volatile("cp.async.wait_group 0;" ::: "memory");
        __syncthreads();

        // prefetch chunk c+1
        if (c < 31) {
            const int k0 = (c + 1) * 32;
            pa0 = aok[0] ? *(const float4*)(xptr + k0)             : make_float4(0,0,0,0);
            pa1 = aok[1] ? *(const float4*)(xptr + 32 * DDIM + k0) : make_float4(0,0,0,0);
            pa2 = aok[2] ? *(const float4*)(xptr + 64 * DDIM + k0) : make_float4(0,0,0,0);
            pa3 = aok[3] ? *(const float4*)(xptr + 96 * DDIM + k0) : make_float4(0,0,0,0);
            uint32_t nb = sb_base + (uint32_t)(buf ^ 1) * bufstride;
            uint32_t d0 = nb + (uint32_t)((brow * SROW + bcol8) * 2);
            uint32_t d1 = nb + (uint32_t)(((brow + 64) * SROW + bcol8) * 2);
            asm volatile("cp.async.cg.shared.global [%0], [%1], 16;" :: "r"(d0), "l"(gB + k0) : "memory");
            asm volatile("cp.async.cg.shared.global [%0], [%1], 16;" :: "r"(d1), "l"(gB + 64 * DDIM + k0) : "memory");
            asm volatile("cp.async.commit_group;" ::: "memory");
        }

        // compute chunk c
        const uint32_t sa = sa_base + buf * bufstride;
        const uint32_t sb = sb_base + buf * bufstride;
#pragma unroll
        for (int ks = 0; ks < 2; ks++) {
            uint32_t a[4][4];
#pragma unroll
            for (int mi = 0; mi < 4; mi++) {
                uint32_t addr = sa + (((wm * 64 + mi * 16 + arow_l) * SROW) + ks * 16 + acol_l) * 2;
                asm volatile("ldmatrix.sync.aligned.m8n8.x4.shared.b16 {%0,%1,%2,%3}, [%4];"
                    : "=r"(a[mi][0]), "=r"(a[mi][1]), "=r"(a[mi][2]), "=r"(a[mi][3]) : "r"(addr));
            }
            uint32_t b[4][2];
#pragma unroll
            for (int njp = 0; njp < 2; njp++) {
                uint32_t addr = sb + (((wn * 32 + njp * 16 + brow_l) * SROW) + ks * 16 + bcol_l) * 2;
                uint32_t r0, r1, r2, r3;
                asm volatile("ldmatrix.sync.aligned.m8n8.x4.shared.b16 {%0,%1,%2,%3}, [%4];"
                    : "=r"(r0), "=r"(r1), "=r"(r2), "=r"(r3) : "r"(addr));
                b[njp * 2 + 0][0] = r0; b[njp * 2 + 0][1] = r1;
                b[njp * 2 + 1][0] = r2; b[njp * 2 + 1][1] = r3;
            }
#pragma unroll
            for (int mi = 0; mi < 4; mi++)
#pragma unroll
                for (int nj = 0; nj < 4; nj++) {
                    asm volatile(
                        "mma.sync.aligned.m16n8k16.row.col.f32.bf16.bf16.f32 "
                        "{%0,%1,%2,%3}, {%4,%5,%6,%7}, {%8,%9}, {%0,%1,%2,%3};"
                        : "+f"(acc[mi][nj][0]), "+f"(acc[mi][nj][1]),
                          "+f"(acc[mi][nj][2]), "+f"(acc[mi][nj][3])
                        : "r"(a[mi][0]), "r"(a[mi][1]), "r"(a[mi][2]), "r"(a[mi][3]),
                          "r"(b[nj][0]), "r"(b[nj][1]));
                }
        }
        __syncthreads();
    }

    // ---- epilogue: score = sum_n tanh(D + b1[n]) * w2[n] ----
#pragma unroll
    for (int mi = 0; mi < 4; mi++) {
        float p0 = 0.f, p1 = 0.f;
#pragma unroll
        for (int nj = 0; nj < 4; nj++) {
            int col = wn * 32 + nj * 8 + (lane & 3) * 2;
            float th;
            float v0 = acc[mi][nj][0] + s_b1[col];
            asm("tanh.approx.f32 %0, %1;" : "=f"(th) : "f"(v0));
            p0 = fmaf(th, s_w2[col], p0);
            float v1 = acc[mi][nj][1] + s_b1[col + 1];
            asm("tanh.approx.f32 %0, %1;" : "=f"(th) : "f"(v1));
            p0 = fmaf(th, s_w2[col + 1], p0);
            float v2 = acc[mi][nj][2] + s_b1[col];
            asm("tanh.approx.f32 %0, %1;" : "=f"(th) : "f"(v2));
            p1 = fmaf(th, s_w2[col], p1);
            float v3 = acc[mi][nj][3] + s_b1[col + 1];
            asm("tanh.approx.f32 %0, %1;" : "=f"(th) : "f"(v3));
            p1 = fmaf(th, s_w2[col + 1], p1);
        }
        p0 += __shfl_xor_sync(0xffffffffu, p0, 1);
        p0 += __shfl_xor_sync(0xffffffffu, p0, 2);
        p1 += __shfl_xor_sync(0xffffffffu, p1, 1);
        p1 += __shfl_xor_sync(0xffffffffu, p1, 2);
        if ((lane & 3) == 0) {
            int r = wm * 64 + mi * 16 + (lane >> 2);
            s_part[wn][r]     = p0;
            s_part[wn][r + 8] = p1;
        }
    }
    __syncthreads();
    if (t < 128) {
        size_t m = block_m + (size_t)t;
        if (m < N_ROWS) {
            float sc = s_part[0][t] + s_part[1][t] + s_part[2][t] + s_part[3][t] + ba2[0];
            g_scores[m] = sc;
            atomicAdd(&g_hist[fliporder(sc) >> 16], 1u);   // fused histogram
        }
    }
}

// ================= threshold scan =================
__global__ void __launch_bounds__(256) scan_k() {
    __shared__ unsigned part[256];
    __shared__ unsigned segbins[256];
    __shared__ int s_seg;
    __shared__ unsigned s_cum;
    int t = threadIdx.x;
    unsigned sum = 0;
#pragma unroll 8
    for (int j = 0; j < 256; j++) sum += g_hist[t * 256 + j];
    part[t] = sum;
    __syncthreads();
    if (t == 0) {
        unsigned cum = 0; int seg = 255;
        for (; seg > 0; seg--) { if (cum + part[seg] >= 64u) break; cum += part[seg]; }
        s_seg = seg; s_cum = cum;
    }
    __syncthreads();
    segbins[t] = g_hist[s_seg * 256 + t];
    __syncthreads();
    if (t == 0) {
        unsigned cum = s_cum; int b = 255;
        for (; b > 0; b--) { cum += segbins[b]; if (cum >= 64u) break; }
        g_thresh = ((unsigned)(s_seg * 256 + b)) << 16;
    }
}

__global__ void __launch_bounds__(512) collect_k() {
    int i = blockIdx.x * 512 + threadIdx.x;
    if (i < N_ROWS && fliporder(g_scores[i]) >= g_thresh) {
        int p = atomicAdd(&g_ncand, 1);
        if (p < MAXC) g_cand_i[p] = i;
    }
}

// ================= exact fp32 rescore of candidates =================
__global__ void __launch_bounds__(128) rescore_k(
    const float* __restrict__ x, const float* __restrict__ Wa1,
    const float* __restrict__ ba1, const float* __restrict__ Wa2,
    const float* __restrict__ ba2)
{
    __shared__ float sx[DDIM];
    __shared__ float sred[4];
    int nc = g_ncand; if (nc > MAXC) nc = MAXC;
    const int t = threadIdx.x;
    for (int c = blockIdx.x; c < nc; c += gridDim.x) {
        int row = g_cand_i[c];
        for (int j = t; j < DDIM; j += 128) sx[j] = x[(size_t)row * DDIM + j];
        __syncthreads();
        float a = 0.f;
#pragma unroll 8
        for (int k = 0; k < DDIM; k++)
            a = fmaf(sx[k], Wa1[(size_t)k * ADIM + t], a);
        float v = tanhf(a + ba1[t]) * Wa2[t];
#pragma unroll
        for (int off = 16; off >= 1; off >>= 1) v += __shfl_down_sync(0xffffffffu, v, off);
        if ((t & 31) == 0) sred[t >> 5] = v;
        __syncthreads();
        if (t == 0) g_cand_v[c] = sred[0] + sred[1] + sred[2] + sred[3] + ba2[0];
        __syncthreads();
    }
}

// ================= exact final top-16 + softmax + scatter =================
__global__ void __launch_bounds__(256) final_k(float* __restrict__ out) {
    __shared__ float sv[MAXC];
    __shared__ int   si[MAXC];
    __shared__ float wv[8];
    __shared__ int   wi[8];
    __shared__ float topv[KSEL];
    __shared__ int   topi[KSEL];
    const int t = threadIdx.x;
    int nc = g_ncand; if (nc > MAXC) nc = MAXC;
    for (int i = t; i < nc; i += 256) { sv[i] = g_cand_v[i]; si[i] = g_cand_i[i]; }
    __syncthreads();
    for (int it = 0; it < KSEL; it++) {
        float bv = -FLT_MAX; int bi = 0x7fffffff;
        for (int i = t; i < nc; i += 256) {
            float v = sv[i]; int gi = si[i];
            if (v > bv || (v == bv && gi < bi)) { bv = v; bi = gi; }
        }
#pragma unroll
        for (int off = 16; off >= 1; off >>= 1) {
            float ov = __shfl_down_sync(0xffffffffu, bv, off);
            int   oi = __shfl_down_sync(0xffffffffu, bi, off);
            if (ov > bv || (ov == bv && oi < bi)) { bv = ov; bi = oi; }
        }
        if ((t & 31) == 0) { wv[t >> 5] = bv; wi[t >> 5] = bi; }
        __syncthreads();
        if (t == 0) {
            for (int w = 1; w < 8; w++)
                if (wv[w] > wv[0] || (wv[w] == wv[0] && wi[w] < wi[0])) { wv[0] = wv[w]; wi[0] = wi[w]; }
            topv[it] = wv[0]; topi[it] = wi[0];
        }
        __syncthreads();
        int wini = topi[it];
        for (int i = t; i < nc; i += 256)
            if (si[i] == wini) sv[i] = -FLT_MAX;
        __syncthreads();
    }
    if (t == 0) {
        float m = topv[0];
        float e[KSEL];
        float ssum = 0.f;
        for (int j = 0; j < KSEL; j++) { e[j] = expf(topv[j] - m); ssum += e[j]; }
        float inv = 1.f / ssum;
        for (int j = 0; j < KSEL; j++) {
            float w = e[j] * inv;
            g_attnw[j]  = w;
            g_topidx[j] = topi[j];
            out[1 + DDIM + N_ROWS + j] = (float)topi[j];
            out[1 + DDIM + topi[j]]    = w;
        }
    }
}

// ================= embedding + classifier =================
__global__ void __launch_bounds__(256) emb_kernel(const float* __restrict__ x,
                                                  float* __restrict__ out) {
    __shared__ float w[KSEL];
    __shared__ int   id[KSEL];
    const int t = threadIdx.x;
    if (t < KSEL) { w[t] = g_attnw[t]; id[t] = g_topidx[t]; }
    __syncthreads();
    for (int d = t; d < DDIM; d += 256) {
        float s = 0.f;
#pragma unroll
        for (int j = 0; j < KSEL; j++)
            s += w[j] * x[(size_t)id[j] * DDIM + d];
        g_emb[d]   = s;
        out[1 + d] = s;
    }
}

__global__ void __launch_bounds__(256) cls_kernel(
    const float* __restrict__ Wc1, const float* __restrict__ bc1,
    const float* __restrict__ Wc2, const float* __restrict__ bc2,
    float* __restrict__ out)
{
    __shared__ float e[DDIM];
    __shared__ float red[256];
    const int t = threadIdx.x;
    for (int d = t; d < DDIM; d += 256) e[d] = g_emb[d];
    __syncthreads();
    float acc = 0.f;
#pragma unroll 8
    for (int d = 0; d < DDIM; d++)
        acc = fmaf(e[d], Wc1[(size_t)d * HDIM + t], acc);
    float h = fmaxf(acc + bc1[t], 0.f);
    red[t] = h * Wc2[t];
    __syncthreads();
    for (int s = 128; s >= 1; s >>= 1) {
        if (t < s) red[t] += red[t + s];
        __syncthreads();
    }
    if (t == 0) out[0] = red[0] + bc2[0];
}

// ================= launch =================
extern "C" void kernel_launch(void* const* d_in, const int* in_sizes, int n_in,
                              void* d_out, int out_size)
{
    const float* x   = (const float*)d_in[0];
    const float* Wa1 = (const float*)d_in[1];
    const float* ba1 = (const float*)d_in[2];
    const float* Wa2 = (const float*)d_in[3];
    const float* ba2 = (const float*)d_in[4];
    const float* Wc1 = (const float*)d_in[5];
    const float* bc1 = (const float*)d_in[6];
    const float* Wc2 = (const float*)d_in[7];
    const float* bc2 = (const float*)d_in[8];
    float* out = (float*)d_out;

    conv_B<<<512, 256>>>(Wa1);
    zero_misc<<<391, 256>>>(out);
    gemm_scores<<<GEMM_BLKS, 256>>>(x, ba1, Wa2, ba2);
    scan_k<<<1, 256>>>();
    collect_k<<<(N_ROWS + 511) / 512, 512>>>();
    rescore_k<<<128, 128>>>(x, Wa1, ba1, Wa2, ba2);
    final_k<<<1, 256>>>(out);
    emb_kernel<<<1, 256>>>(x, out);
    cls_kernel<<<1, 256>>>(Wc1, bc1, Wc2, bc2, out);
}

// round 6
// speedup vs baseline: 4.4353x; 1.4464x over previous
#include <cuda_runtime.h>
#include <cuda_bf16.h>
#include <math.h>
#include <float.h>
#include <stdint.h>

#define N_ROWS 100000
#define DDIM 1024
#define ADIM 128
#define HDIM 256
#define KSEL 16
#define MAXC 4096
#define NHIST 8192
#define HSHIFT 19
#define GEMM_BLKS 782       // ceil(100000/128)

// ================= scratch (device globals; no allocation) =================
__device__ float g_scores[N_ROWS];
__device__ __align__(16) __nv_bfloat16 g_Bbf[ADIM * DDIM];   // Wa1^T, bf16, [n][k]
__device__ unsigned g_hist[NHIST];
__device__ int      g_ncand;
__device__ unsigned g_thresh;
__device__ int      g_cand_i[MAXC];
__device__ float    g_cand_v[MAXC];
__device__ int      g_topidx[KSEL];
__device__ float    g_attnw[KSEL];
__device__ float    g_emb[DDIM];

__device__ __forceinline__ uint32_t smem_u32(const void* p) {
    uint32_t a;
    asm("{ .reg .u64 tmp; cvta.to.shared.u64 tmp, %1; cvt.u32.u64 %0, tmp; }"
        : "=r"(a) : "l"(p));
    return a;
}

__device__ __forceinline__ unsigned fliporder(float f) {
    unsigned u = __float_as_uint(f);
    return (u & 0x80000000u) ? ~u : (u | 0x80000000u);
}

// ================= pre-pass: Wa1 [k][n] fp32 -> g_Bbf [n][k] bf16 =================
__global__ void __launch_bounds__(256) conv_B(const float* __restrict__ Wa1) {
    int idx = blockIdx.x * 256 + threadIdx.x;   // 0..131071
    int n = idx & 127;
    int k = idx >> 7;
    g_Bbf[(size_t)n * DDIM + k] = __float2bfloat16(Wa1[(size_t)k * ADIM + n]);
}

// ================= zero: full_weights + histogram + counter + logit seed =================
__global__ void __launch_bounds__(256) zero_misc(float* __restrict__ out,
                                                 const float* __restrict__ bc2) {
    int i = blockIdx.x * 256 + threadIdx.x;
    if (i < N_ROWS) out[1 + DDIM + i] = 0.f;
    if (i < NHIST)  g_hist[i] = 0u;
    if (i == 0)   { g_ncand = 0; out[0] = bc2[0]; }
}

// ================= main GEMM: approx scores via mma.sync bf16 =================
// BM=128, BN=128(=ADIM), BK=32, 256 threads = 8 warps (2 M-halves x 4 N-slices),
// warp tile 64x32, double-buffered smem, ONE sync per chunk, cp.async B, 2 CTAs/SM.
#define SROW 40   // padded row stride (bf16); 80B rows, 16B-aligned offsets

__global__ void __launch_bounds__(256, 2) gemm_scores(
    const float* __restrict__ x, const float* __restrict__ ba1,
    const float* __restrict__ Wa2, const float* __restrict__ ba2)
{
    __shared__ __align__(16) __nv_bfloat16 sA[2][128][SROW];
    __shared__ __align__(16) __nv_bfloat16 sB[2][128][SROW];
    __shared__ float s_part[4][128];
    __shared__ float s_b1[ADIM], s_w2[ADIM];

    const int t = threadIdx.x;
    const int w = t >> 5, lane = t & 31;
    const int wm = w & 1, wn = w >> 1;          // wm: M-half (64 rows), wn: N-slice (32 cols)
    const size_t block_m = (size_t)blockIdx.x * 128;

    if (t < ADIM) { s_b1[t] = ba1[t]; s_w2[t] = Wa2[t]; }

    // A global-load mapping: 4 slots/thread, slot i -> row arow+32*i, cols acol..acol+3
    const int arow = t >> 3;                    // 0..31
    const int acol = (t & 7) * 4;               // 0..28
    const float* xptr = x + (block_m + (size_t)arow) * DDIM + acol;
    bool aok[4];
#pragma unroll
    for (int i = 0; i < 4; i++) aok[i] = (block_m + arow + 32 * i) < N_ROWS;

    // B cp.async mapping: 2 slots/thread, slot j -> row brow+64*j, 16B at bcol8
    const int brow = t >> 2;                    // 0..63
    const int bcol8 = (t & 3) * 8;              // bf16 col offset 0,8,16,24
    const __nv_bfloat16* gB = g_Bbf + (size_t)brow * DDIM + bcol8;

    // ldmatrix lane address components
    const int arow_l = ((lane >> 3) & 1) * 8 + (lane & 7);
    const int acol_l = (lane >> 4) * 8;
    const int brow_l = ((lane >> 4) & 1) * 8 + (lane & 7);
    const int bcol_l = ((lane >> 3) & 1) * 8;

    const uint32_t sa_base = smem_u32(&sA[0][0][0]);
    const uint32_t sb_base = smem_u32(&sB[0][0][0]);
    const uint32_t bufstride = 128 * SROW * 2;

    float acc[4][4][4];
#pragma unroll
    for (int i = 0; i < 4; i++)
#pragma unroll
        for (int j = 0; j < 4; j++)
#pragma unroll
            for (int q = 0; q < 4; q++) acc[i][j][q] = 0.f;

    // ---- prologue: A(0) -> regs, B(0) -> sB[0] ----
    float4 pa0, pa1, pa2, pa3;
    pa0 = aok[0] ? *(const float4*)(xptr)               : make_float4(0,0,0,0);
    pa1 = aok[1] ? *(const float4*)(xptr + 32 * DDIM)   : make_float4(0,0,0,0);
    pa2 = aok[2] ? *(const float4*)(xptr + 64 * DDIM)   : make_float4(0,0,0,0);
    pa3 = aok[3] ? *(const float4*)(xptr + 96 * DDIM)   : make_float4(0,0,0,0);
    {
        uint32_t d0 = sb_base + (uint32_t)((brow * SROW + bcol8) * 2);
        uint32_t d1 = sb_base + (uint32_t)(((brow + 64) * SROW + bcol8) * 2);
        asm volatile("cp.async.cg.shared.global [%0], [%1], 16;" :: "r"(d0), "l"(gB) : "memory");
        asm volatile("cp.async.cg.shared.global [%0], [%1], 16;" :: "r"(d1), "l"(gB + 64 * DDIM) : "memory");
        asm volatile("cp.async.commit_group;" ::: "memory");
    }

#pragma unroll 1
    for (int c = 0; c < 32; c++) {
        const int buf = c & 1;
        // 1. store A(c) regs -> sA[buf] (safe: last read of sA[buf] drained by sync at c-1)
        {
            __nv_bfloat16* base = &sA[buf][0][0];
            __nv_bfloat162 q0 = __floats2bfloat162_rn(pa0.x, pa0.y);
            __nv_bfloat162 q1 = __floats2bfloat162_rn(pa0.z, pa0.w);
            *(uint2*)(base + arow * SROW + acol) = make_uint2(*(uint32_t*)&q0, *(uint32_t*)&q1);
            q0 = __floats2bfloat162_rn(pa1.x, pa1.y); q1 = __floats2bfloat162_rn(pa1.z, pa1.w);
            *(uint2*)(base + (arow + 32) * SROW + acol) = make_uint2(*(uint32_t*)&q0, *(uint32_t*)&q1);
            q0 = __floats2bfloat162_rn(pa2.x, pa2.y); q1 = __floats2bfloat162_rn(pa2.z, pa2.w);
            *(uint2*)(base + (arow + 64) * SROW + acol) = make_uint2(*(uint32_t*)&q0, *(uint32_t*)&q1);
            q0 = __floats2bfloat162_rn(pa3.x, pa3.y); q1 = __floats2bfloat162_rn(pa3.z, pa3.w);
            *(uint2*)(base + (arow + 96) * SROW + acol) = make_uint2(*(uint32_t*)&q0, *(uint32_t*)&q1);
        }
        // 2. LDG A(c+1) -> regs (WAR on pa* resolved at STS issue)
        if (c < 31) {
            const int k0 = (c + 1) * 32;
            pa0 = aok[0] ? *(const float4*)(xptr + k0)             : make_float4(0,0,0,0);
            pa1 = aok[1] ? *(const float4*)(xptr + 32 * DDIM + k0) : make_float4(0,0,0,0);
            pa2 = aok[2] ? *(const float4*)(xptr + 64 * DDIM + k0) : make_float4(0,0,0,0);
            pa3 = aok[3] ? *(const float4*)(xptr + 96 * DDIM + k0) : make_float4(0,0,0,0);
        }
        // 3. wait for B(c) (only outstanding group; committed a full chunk ago)
        asm volatile("cp.async.wait_group 0;" ::: "memory");
        // 4. single barrier: A stores visible, B(c) visible, compute c-1 reads drained
        __syncthreads();
        // 5. issue B(c+1) into sB[buf^1] (its last reader, compute c-1, drained by sync above)
        if (c < 31) {
            const int k0 = (c + 1) * 32;
            uint32_t nb = sb_base + (uint32_t)(buf ^ 1) * bufstride;
            uint32_t d0 = nb + (uint32_t)((brow * SROW + bcol8) * 2);
            uint32_t d1 = nb + (uint32_t)(((brow + 64) * SROW + bcol8) * 2);
            asm volatile("cp.async.cg.shared.global [%0], [%1], 16;" :: "r"(d0), "l"(gB + k0) : "memory");
            asm volatile("cp.async.cg.shared.global [%0], [%1], 16;" :: "r"(d1), "l"(gB + 64 * DDIM + k0) : "memory");
            asm volatile("cp.async.commit_group;" ::: "memory");
        }
        // 6. compute chunk c
        const uint32_t sa = sa_base + buf * bufstride;
        const uint32_t sb = sb_base + buf * bufstride;
#pragma unroll
        for (int ks = 0; ks < 2; ks++) {
            uint32_t a[4][4];
#pragma unroll
            for (int mi = 0; mi < 4; mi++) {
                uint32_t addr = sa + (((wm * 64 + mi * 16 + arow_l) * SROW) + ks * 16 + acol_l) * 2;
                asm volatile("ldmatrix.sync.aligned.m8n8.x4.shared.b16 {%0,%1,%2,%3}, [%4];"
                    : "=r"(a[mi][0]), "=r"(a[mi][1]), "=r"(a[mi][2]), "=r"(a[mi][3]) : "r"(addr));
            }
            uint32_t b[4][2];
#pragma unroll
            for (int njp = 0; njp < 2; njp++) {
                uint32_t addr = sb + (((wn * 32 + njp * 16 + brow_l) * SROW) + ks * 16 + bcol_l) * 2;
                uint32_t r0, r1, r2, r3;
                asm volatile("ldmatrix.sync.aligned.m8n8.x4.shared.b16 {%0,%1,%2,%3}, [%4];"
                    : "=r"(r0), "=r"(r1), "=r"(r2), "=r"(r3) : "r"(addr));
                b[njp * 2 + 0][0] = r0; b[njp * 2 + 0][1] = r1;
                b[njp * 2 + 1][0] = r2; b[njp * 2 + 1][1] = r3;
            }
#pragma unroll
            for (int mi = 0; mi < 4; mi++)
#pragma unroll
                for (int nj = 0; nj < 4; nj++) {
                    asm volatile(
                        "mma.sync.aligned.m16n8k16.row.col.f32.bf16.bf16.f32 "
                        "{%0,%1,%2,%3}, {%4,%5,%6,%7}, {%8,%9}, {%0,%1,%2,%3};"
                        : "+f"(acc[mi][nj][0]), "+f"(acc[mi][nj][1]),
                          "+f"(acc[mi][nj][2]), "+f"(acc[mi][nj][3])
                        : "r"(a[mi][0]), "r"(a[mi][1]), "r"(a[mi][2]), "r"(a[mi][3]),
                          "r"(b[nj][0]), "r"(b[nj][1]));
                }
        }
    }

    // ---- epilogue: score = sum_n tanh(D + b1[n]) * w2[n], fused histogram ----
    __syncthreads();   // all compute done before s_part reuse
#pragma unroll
    for (int mi = 0; mi < 4; mi++) {
        float p0 = 0.f, p1 = 0.f;
#pragma unroll
        for (int nj = 0; nj < 4; nj++) {
            int col = wn * 32 + nj * 8 + (lane & 3) * 2;
            float th;
            float v0 = acc[mi][nj][0] + s_b1[col];
            asm("tanh.approx.f32 %0, %1;" : "=f"(th) : "f"(v0));
            p0 = fmaf(th, s_w2[col], p0);
            float v1 = acc[mi][nj][1] + s_b1[col + 1];
            asm("tanh.approx.f32 %0, %1;" : "=f"(th) : "f"(v1));
            p0 = fmaf(th, s_w2[col + 1], p0);
            float v2 = acc[mi][nj][2] + s_b1[col];
            asm("tanh.approx.f32 %0, %1;" : "=f"(th) : "f"(v2));
            p1 = fmaf(th, s_w2[col], p1);
            float v3 = acc[mi][nj][3] + s_b1[col + 1];
            asm("tanh.approx.f32 %0, %1;" : "=f"(th) : "f"(v3));
            p1 = fmaf(th, s_w2[col + 1], p1);
        }
        p0 += __shfl_xor_sync(0xffffffffu, p0, 1);
        p0 += __shfl_xor_sync(0xffffffffu, p0, 2);
        p1 += __shfl_xor_sync(0xffffffffu, p1, 1);
        p1 += __shfl_xor_sync(0xffffffffu, p1, 2);
        if ((lane & 3) == 0) {
            int r = wm * 64 + mi * 16 + (lane >> 2);
            s_part[wn][r]     = p0;
            s_part[wn][r + 8] = p1;
        }
    }
    __syncthreads();
    if (t < 128) {
        size_t m = block_m + (size_t)t;
        if (m < N_ROWS) {
            float sc = s_part[0][t] + s_part[1][t] + s_part[2][t] + s_part[3][t] + ba2[0];
            g_scores[m] = sc;
            atomicAdd(&g_hist[fliporder(sc) >> HSHIFT], 1u);
        }
    }
}

// ================= threshold scan (8192 bins) =================
__global__ void __launch_bounds__(256) scan_k() {
    __shared__ unsigned part[256];
    __shared__ unsigned segbins[32];
    __shared__ int s_seg;
    __shared__ unsigned s_cum;
    int t = threadIdx.x;
    unsigned sum = 0;
#pragma unroll
    for (int j = 0; j < 32; j++) sum += g_hist[t * 32 + j];
    part[t] = sum;
    __syncthreads();
    if (t == 0) {
        unsigned cum = 0; int seg = 255;
        for (; seg > 0; seg--) { if (cum + part[seg] >= 64u) break; cum += part[seg]; }
        s_seg = seg; s_cum = cum;
    }
    __syncthreads();
    if (t < 32) segbins[t] = g_hist[s_seg * 32 + t];
    __syncthreads();
    if (t == 0) {
        unsigned cum = s_cum; int b = 31;
        for (; b > 0; b--) { cum += segbins[b]; if (cum >= 64u) break; }
        g_thresh = ((unsigned)(s_seg * 32 + b)) << HSHIFT;
    }
}

__global__ void __launch_bounds__(512) collect_k() {
    int i = blockIdx.x * 512 + threadIdx.x;
    if (i < N_ROWS && fliporder(g_scores[i]) >= g_thresh) {
        int p = atomicAdd(&g_ncand, 1);
        if (p < MAXC) g_cand_i[p] = i;
    }
}

// ================= exact fp32 rescore of candidates =================
__global__ void __launch_bounds__(128) rescore_k(
    const float* __restrict__ x, const float* __restrict__ Wa1,
    const float* __restrict__ ba1, const float* __restrict__ Wa2,
    const float* __restrict__ ba2)
{
    __shared__ float sx[DDIM];
    __shared__ float sred[4];
    int nc = g_ncand; if (nc > MAXC) nc = MAXC;
    const int t = threadIdx.x;
    for (int c = blockIdx.x; c < nc; c += gridDim.x) {
        int row = g_cand_i[c];
        for (int j = t; j < DDIM; j += 128) sx[j] = x[(size_t)row * DDIM + j];
        __syncthreads();
        float a = 0.f;
#pragma unroll 8
        for (int k = 0; k < DDIM; k++)
            a = fmaf(sx[k], Wa1[(size_t)k * ADIM + t], a);
        float v = tanhf(a + ba1[t]) * Wa2[t];
#pragma unroll
        for (int off = 16; off >= 1; off >>= 1) v += __shfl_down_sync(0xffffffffu, v, off);
        if ((t & 31) == 0) sred[t >> 5] = v;
        __syncthreads();
        if (t == 0) g_cand_v[c] = sred[0] + sred[1] + sred[2] + sred[3] + ba2[0];
        __syncthreads();
    }
}

// ================= tail: exact top-16 + softmax + scatter + embedding =================
__global__ void __launch_bounds__(256) tail_k(const float* __restrict__ x,
                                              float* __restrict__ out) {
    __shared__ float sv[MAXC];
    __shared__ int   si[MAXC];
    __shared__ float wv[8];
    __shared__ int   wi[8];
    __shared__ float topv[KSEL];
    __shared__ int   topi[KSEL];
    __shared__ float topw[KSEL];
    const int t = threadIdx.x;
    int nc = g_ncand; if (nc > MAXC) nc = MAXC;
    for (int i = t; i < nc; i += 256) { sv[i] = g_cand_v[i]; si[i] = g_cand_i[i]; }
    __syncthreads();
    for (int it = 0; it < KSEL; it++) {
        float bv = -FLT_MAX; int bi = 0x7fffffff;
        for (int i = t; i < nc; i += 256) {
            float v = sv[i]; int gi = si[i];
            if (v > bv || (v == bv && gi < bi)) { bv = v; bi = gi; }
        }
#pragma unroll
        for (int off = 16; off >= 1; off >>= 1) {
            float ov = __shfl_down_sync(0xffffffffu, bv, off);
            int   oi = __shfl_down_sync(0xffffffffu, bi, off);
            if (ov > bv || (ov == bv && oi < bi)) { bv = ov; bi = oi; }
        }
        if ((t & 31) == 0) { wv[t >> 5] = bv; wi[t >> 5] = bi; }
        __syncthreads();
        if (t == 0) {
            for (int w = 1; w < 8; w++)
                if (wv[w] > wv[0] || (wv[w] == wv[0] && wi[w] < wi[0])) { wv[0] = wv[w]; wi[0] = wi[w]; }
            topv[it] = wv[0]; topi[it] = wi[0];
        }
        __syncthreads();
        int wini = topi[it];
        for (int i = t; i < nc; i += 256)
            if (si[i] == wini) sv[i] = -FLT_MAX;
        __syncthreads();
    }
    if (t == 0) {
        float m = topv[0];
        float e[KSEL];
        float ssum = 0.f;
        for (int j = 0; j < KSEL; j++) { e[j] = expf(topv[j] - m); ssum += e[j]; }
        float inv = 1.f / ssum;
        for (int j = 0; j < KSEL; j++) {
            float wgt = e[j] * inv;
            topw[j] = wgt;
            g_attnw[j]  = wgt;
            g_topidx[j] = topi[j];
            out[1 + DDIM + N_ROWS + j] = (float)topi[j];
            out[1 + DDIM + topi[j]]    = wgt;
        }
    }
    __syncthreads();
    // embedding: attn_w @ x[top_idx]
    for (int d = t; d < DDIM; d += 256) {
        float s = 0.f;
#pragma unroll
        for (int j = 0; j < KSEL; j++)
            s += topw[j] * x[(size_t)topi[j] * DDIM + d];
        g_emb[d]   = s;
        out[1 + d] = s;
    }
}

// ================= classifier: 8 blocks, partial logits via atomicAdd =================
__global__ void __launch_bounds__(256) cls_kernel(
    const float* __restrict__ Wc1, const float* __restrict__ bc1,
    const float* __restrict__ Wc2, float* __restrict__ out)
{
    __shared__ float e[DDIM];
    __shared__ float sred[8][32];
    const int t = threadIdx.x;
    const int j = blockIdx.x * 32 + (t & 31);   // h index, coalesced across lane
    const int dp = (t >> 5) * 128;              // d-slice per warp
    for (int d = t; d < DDIM; d += 256) e[d] = g_emb[d];
    __syncthreads();
    float acc = 0.f;
#pragma unroll 16
    for (int d = 0; d < 128; d++)
        acc = fmaf(e[dp + d], Wc1[(size_t)(dp + d) * HDIM + j], acc);
    sred[t >> 5][t & 31] = acc;
    __syncthreads();
    if (t < 32) {
        float a = sred[0][t] + sred[1][t] + sred[2][t] + sred[3][t]
                + sred[4][t] + sred[5][t] + sred[6][t] + sred[7][t];
        int jj = blockIdx.x * 32 + t;
        float h = fmaxf(a + bc1[jj], 0.f);
        float part = h * Wc2[jj];
#pragma unroll
        for (int off = 16; off >= 1; off >>= 1)
            part += __shfl_down_sync(0xffffffffu, part, off);
        if (t == 0) atomicAdd(out, part);       // out[0] pre-seeded with bc2[0]
    }
}

// ================= launch =================
extern "C" void kernel_launch(void* const* d_in, const int* in_sizes, int n_in,
                              void* d_out, int out_size)
{
    const float* x   = (const float*)d_in[0];
    const float* Wa1 = (const float*)d_in[1];
    const float* ba1 = (const float*)d_in[2];
    const float* Wa2 = (const float*)d_in[3];
    const float* ba2 = (const float*)d_in[4];
    const float* Wc1 = (const float*)d_in[5];
    const float* bc1 = (const float*)d_in[6];
    const float* Wc2 = (const float*)d_in[7];
    const float* bc2 = (const float*)d_in[8];
    float* out = (float*)d_out;

    conv_B<<<512, 256>>>(Wa1);
    zero_misc<<<391, 256>>>(out, bc2);
    gemm_scores<<<GEMM_BLKS, 256>>>(x, ba1, Wa2, ba2);
    scan_k<<<1, 256>>>();
    collect_k<<<(N_ROWS + 511) / 512, 512>>>();
    rescore_k<<<128, 128>>>(x, Wa1, ba1, Wa2, ba2);
    tail_k<<<1, 256>>>(x, out);
    cls_kernel<<<HDIM / 32, 256>>>(Wc1, bc1, Wc2, out);
}